// round 15
// baseline (speedup 1.0000x reference)
#include <cuda_runtime.h>

// ---------------- problem constants ----------------
#define B_      8
#define IN_C    32
#define OUT_C   64
#define H_      64
#define W_      64
#define QDIM    36
#define PDIM    8
#define KB      8
#define NPIX    (B_*H_*W_)          // 32768
#define NQP     (QDIM/2)            // 18 q-pairs
#define WSTR    12                  // u64 entries per (qp,p) packed spectrum

#define HP      66
#define CHW     (HP*HP)             // 4356
#define PAD_TOTAL (B_*IN_C*CHW)     // 1,115,136
#define NROWS   (B_*IN_C*HP)        // 16896 padded rows

#define MRR_A   0.987
#define MRR_R   0.99

typedef unsigned long long u64;

__device__ float g_xpad[PAD_TOTAL];

// ---------------- kernel 1: zero-padded x^2, warp-per-row ----------------
__global__ void prepad_kernel(const float* __restrict__ x) {
    const int warp = (blockIdx.x * blockDim.x + threadIdx.x) >> 5;
    const int lane = threadIdx.x & 31;
    if (warp < NROWS) {
        const int bc = warp / HP;
        const int hp = warp - bc * HP;
        const bool rowin = (hp >= 1) && (hp <= H_);
        const float* __restrict__ xrow = x + (bc * H_ + (hp - 1)) * W_;
        float* __restrict__ orow = g_xpad + warp * HP;

        {
            int wp = lane;
            float v = 0.0f;
            if (rowin && wp >= 1) { float t = xrow[wp - 1]; v = t * t; }
            orow[wp] = v;
        }
        {
            int wp = lane + 32;
            float v = 0.0f;
            if (rowin) { float t = xrow[wp - 1]; v = t * t; }
            orow[wp] = v;
        }
        if (lane < 2) {
            int wp = 64 + lane;
            float v = 0.0f;
            if (rowin && wp <= W_) { float t = xrow[wp - 1]; v = t * t; }
            orow[wp] = v;
        }
    }
#if __CUDA_ARCH__ >= 900
    // allow the dependent morr launch to start its preamble early
    cudaTriggerProgrammaticLaunchCompletion();
#endif
}

// ---------------- packed f32x2 helpers ----------------
__device__ __forceinline__ u64 pack2(float a, float b) {
    u64 r; asm("mov.b64 %0, {%1, %2};" : "=l"(r) : "f"(a), "f"(b)); return r;
}
__device__ __forceinline__ void unpack2(u64 v, float& a, float& b) {
    asm("mov.b64 {%0, %1}, %2;" : "=f"(a), "=f"(b) : "l"(v));
}
__device__ __forceinline__ u64 add2(u64 a, u64 b) {
    u64 r; asm("add.rn.f32x2 %0, %1, %2;" : "=l"(r) : "l"(a), "l"(b)); return r;
}
__device__ __forceinline__ u64 sub2(u64 a, u64 b) {
    u64 r; asm("sub.rn.f32x2 %0, %1, %2;" : "=l"(r) : "l"(a), "l"(b)); return r;
}
__device__ __forceinline__ u64 mul2(u64 a, u64 b) {
    u64 r; asm("mul.rn.f32x2 %0, %1, %2;" : "=l"(r) : "l"(a), "l"(b)); return r;
}
__device__ __forceinline__ u64 fma2(u64 a, u64 b, u64 c) {
    u64 r; asm("fma.rn.f32x2 %0, %1, %2, %3;" : "=l"(r) : "l"(a), "l"(b), "l"(c)); return r;
}

// 8-pt real FFT of |w| row, scales folded (bins 0,4 -> 1/8; bins 1-3 -> 1/4)
__device__ __forceinline__ void wspec(const float* __restrict__ wrow, float o[12]) {
    float x[8];
#pragma unroll
    for (int s = 0; s < 8; ++s) x[s] = fabsf(wrow[s]);
    float s0 = x[0] + x[4], s1 = x[0] - x[4], s2 = x[2] + x[6], s3 = x[2] - x[6];
    float t0 = x[1] + x[5], t1 = x[1] - x[5], t2 = x[3] + x[7], t3 = x[3] - x[7];
    float E0 = s0 + s2, O0 = t0 + t2;
    const float Cc = 0.70710678118654752f;
    float u = Cc * (t1 - t3), v = Cc * (t1 + t3);
    o[0]  = (E0 + O0) * 0.125f;
    o[1]  = (E0 - O0) * 0.125f;
    o[2]  = (s1 + u) * 0.25f;  o[3] = (-s3 - v) * 0.25f;  o[4]  = -o[3];
    o[5]  = (s0 - s2) * 0.25f; o[6] = (t2 - t0) * 0.25f;  o[7]  = -o[6];
    o[8]  = (s1 - u) * 0.25f;  o[9] = (s3 - v) * 0.25f;   o[10] = -o[9];
    o[11] = 0.0f;
}

// shared-rcp epilogue for a butterfly pair (4 phases, ONE rcp)
#define PAIR_EPILOGUE(YA, YB, ACCA, ACCB) do {                       \
    float phA0, phA1, phB0, phB1;                                    \
    unpack2((YA), phA0, phA1);                                       \
    unpack2((YB), phB0, phB1);                                       \
    float cA0 = __cosf(phA0), cA1 = __cosf(phA1);                    \
    float cB0 = __cosf(phB0), cB1 = __cosf(phB1);                    \
    float eA0 = fmaf(cA0, N2AR, C2), eA1 = fmaf(cA1, N2AR, C2);      \
    float eB0 = fmaf(cB0, N2AR, C2), eB1 = fmaf(cB1, N2AR, C2);      \
    float numA = fmaf(a1, eA0, a0 * eA1);                            \
    float denA = eA0 * eA1;                                          \
    float numB = fmaf(a1, eB0, a0 * eB1);                            \
    float denB = eB0 * eB1;                                          \
    float rr;                                                        \
    asm("rcp.approx.f32 %0, %1;" : "=f"(rr) : "f"(denA * denB));     \
    (ACCA) = fmaf(numA * denB, rr, (ACCA));                          \
    (ACCB) = fmaf(numB * denA, rr, (ACCB));                          \
} while (0)

// ---------------- kernel 2: main compute (R11 chassis + PDL sync) ----------
// grid 1024, block 128. warp -> psplit (2 p's per thread), lane -> pixel.
__global__ __launch_bounds__(128, 7) void morr_kernel(const float* __restrict__ wgt,
                                                      const float* __restrict__ mos,
                                                      float* __restrict__ out) {
    __shared__ u64   wpk[NQP * PDIM * WSTR];  // packed {q0,q1} spectra, 13824 B
    __shared__ int   poff[QDIM * KB];
    __shared__ float scl[QDIM];

    const int tid = threadIdx.x;

    // ---- preamble: consumes only wgt/mos, overlaps with prepad via PDL ----
    for (int d = tid; d < NQP * PDIM; d += 128) {
        int qp = d >> 3;
        int p  = d & 7;
        float sA[12], sB[12];
        wspec(wgt + p * (QDIM * KB) + (2 * qp) * KB,     sA);
        wspec(wgt + p * (QDIM * KB) + (2 * qp + 1) * KB, sB);
        u64* o = &wpk[(qp * PDIM + p) * WSTR];
#pragma unroll
        for (int j = 0; j < 12; ++j) o[j] = pack2(sA[j], sB[j]);
    }
    for (int i = tid; i < QDIM * KB; i += 128) {
        int c = i / 9, r = i % 9;
        poff[i] = c * CHW + (r / 3) * HP + (r % 3);
    }
    if (tid < QDIM) {
        const float D = (float)((1.0 - MRR_A * MRR_A) * (1.0 - MRR_R * MRR_R));
        float sv = (tid < QDIM / 2) ? mos[tid] : -mos[tid - QDIM / 2];
        scl[tid] = -D * sv;
    }
    __syncthreads();

#if __CUDA_ARCH__ >= 900
    // wait for prepad's g_xpad stores to be visible before first gather
    cudaGridDependencySynchronize();
#endif

    const int psplit = tid >> 5;
    const int lane   = tid & 31;
    const int n = blockIdx.x * 32 + lane;
    const int b = n >> 12;
    const int h = (n >> 6) & 63;
    const int w = n & 63;

    const float* __restrict__ xb = g_xpad + b * (IN_C * CHW) + h * HP + w;

    float acc[2][8];
#pragma unroll
    for (int pl = 0; pl < 2; ++pl)
#pragma unroll
        for (int t = 0; t < 8; ++t) acc[pl][t] = 0.0f;

    const float C2   = (float)(1.0 + (MRR_A * MRR_R) * (MRR_A * MRR_R));
    const float N2AR = (float)(-2.0 * MRR_A * MRR_R);
    const float Cc = 0.70710678118654752f;
    const u64 CC2  = pack2(Cc, Cc);
    const u64 CCN2 = pack2(-Cc, -Cc);

    for (int qp = 0; qp < NQP; ++qp) {
        const float a0 = scl[2 * qp];
        const float a1 = scl[2 * qp + 1];

        u64 xs[8];
#pragma unroll
        for (int s = 0; s < 8; ++s) {
            float x0 = xb[poff[qp * 16 + s]];
            float x1 = xb[poff[qp * 16 + 8 + s]];
            xs[s] = pack2(x0, x1);
        }

        // forward 8-pt real FFT (packed) — shared across both p's
        u64 s0 = add2(xs[0], xs[4]), s1 = sub2(xs[0], xs[4]);
        u64 s2 = add2(xs[2], xs[6]), s3 = sub2(xs[2], xs[6]);
        u64 t0 = add2(xs[1], xs[5]), t1 = sub2(xs[1], xs[5]);
        u64 t2 = add2(xs[3], xs[7]), t3 = sub2(xs[3], xs[7]);
        u64 E0 = add2(s0, s2), O0 = add2(t0, t2);
        u64 X0  = add2(E0, O0);
        u64 X4  = sub2(E0, O0);
        u64 X2r = sub2(s0, s2);
        u64 X2i = sub2(t2, t0);
        u64 um  = sub2(t1, t3), vp = add2(t1, t3);
        u64 u_  = mul2(CC2, um);
        u64 vn  = mul2(CCN2, vp);
        u64 X1r = add2(s1, u_);
        u64 X1i = sub2(vn, s3);
        u64 X3r = sub2(s1, u_);
        u64 X3i = add2(s3, vn);

#pragma unroll
        for (int pl = 0; pl < 2; ++pl) {
            const int p = psplit * 2 + pl;
            const u64* __restrict__ wq = &wpk[(qp * PDIM + p) * WSTR];

            u64 P0  = mul2(X0, wq[0]);
            u64 P4  = mul2(X4, wq[1]);
            u64 P1r = fma2(X1i, wq[4],  mul2(X1r, wq[2]));
            u64 P1i = fma2(X1r, wq[3],  mul2(X1i, wq[2]));
            u64 P2r = fma2(X2i, wq[7],  mul2(X2r, wq[5]));
            u64 P2i = fma2(X2r, wq[6],  mul2(X2i, wq[5]));
            u64 P3r = fma2(X3i, wq[10], mul2(X3r, wq[8]));
            u64 P3i = fma2(X3r, wq[9],  mul2(X3i, wq[8]));

            u64 A0 = add2(P0, P4), A1 = sub2(P0, P4);
            u64 e0 = add2(A0, P2r), e2 = sub2(A0, P2r);
            u64 e1 = sub2(A1, P2i), e3 = add2(A1, P2i);
            u64 o0 = add2(P1r, P3r);
            u64 o2 = sub2(P3i, P1i);
            u64 u2 = sub2(P1r, P3r), v2 = add2(P1i, P3i);
            u64 o1 = mul2(CC2,  sub2(u2, v2));
            u64 o3 = mul2(CCN2, add2(u2, v2));

            { u64 ya = add2(e0, o0), yb = sub2(e0, o0);
              PAIR_EPILOGUE(ya, yb, acc[pl][0], acc[pl][4]); }
            { u64 ya = add2(e1, o1), yb = sub2(e1, o1);
              PAIR_EPILOGUE(ya, yb, acc[pl][1], acc[pl][5]); }
            { u64 ya = add2(e2, o2), yb = sub2(e2, o2);
              PAIR_EPILOGUE(ya, yb, acc[pl][2], acc[pl][6]); }
            { u64 ya = add2(e3, o3), yb = sub2(e3, o3);
              PAIR_EPILOGUE(ya, yb, acc[pl][3], acc[pl][7]); }
        }
    }

    float* __restrict__ ob = out + (b * OUT_C + psplit * 16) * (H_ * W_) + h * W_ + w;
#pragma unroll
    for (int pl = 0; pl < 2; ++pl)
#pragma unroll
        for (int t = 0; t < 8; ++t)
            ob[(pl * 8 + t) * (H_ * W_)] = acc[pl][t];
}

// ---------------- launch ----------------
extern "C" void kernel_launch(void* const* d_in, const int* in_sizes, int n_in,
                              void* d_out, int out_size) {
    const float* x   = (const float*)d_in[0];
    const float* wgt = (const float*)d_in[1];
    const float* mos = (const float*)d_in[2];
    float* out = (float*)d_out;

    prepad_kernel<<<(NROWS + 7) / 8, 256>>>(x);

    // morr with programmatic dependent launch: preamble overlaps prepad tail
    cudaLaunchConfig_t cfg = {};
    cfg.gridDim  = dim3(NPIX / 32);
    cfg.blockDim = dim3(128);
    cfg.dynamicSmemBytes = 0;
    cudaLaunchAttribute attrs[1];
    attrs[0].id = cudaLaunchAttributeProgrammaticStreamSerialization;
    attrs[0].val.programmaticStreamSerializationAllowed = 1;
    cfg.attrs = attrs;
    cfg.numAttrs = 1;
    cudaError_t err = cudaLaunchKernelEx(&cfg, morr_kernel, wgt, mos, out);
    if (err != cudaSuccess) {
        // fallback: plain serialized launch (identical semantics)
        morr_kernel<<<NPIX / 32, 128>>>(wgt, mos, out);
    }
}

// round 16
// speedup vs baseline: 1.1348x; 1.1348x over previous
#include <cuda_runtime.h>

// ---------------- problem constants ----------------
#define B_      8
#define IN_C    32
#define OUT_C   64
#define H_      64
#define W_      64
#define QDIM    36
#define PDIM    8
#define KB      8
#define NPIX    (B_*H_*W_)          // 32768
#define NQP     (QDIM/2)            // 18 q-pairs
#define WSTR    12                  // u64 entries per (qp,p) packed spectrum

#define CTILE   34                  // tile cols: w0-1 .. w0+32
#define TROWS   3                   // kh = 0..2
#define TILE_N  (IN_C*TROWS*CTILE)  // 3264 floats
#define CSTR    (TROWS*CTILE)       // 102 floats per channel in tile

#define MRR_A   0.987
#define MRR_R   0.99

typedef unsigned long long u64;

// ---------------- packed f32x2 helpers ----------------
__device__ __forceinline__ u64 pack2(float a, float b) {
    u64 r; asm("mov.b64 %0, {%1, %2};" : "=l"(r) : "f"(a), "f"(b)); return r;
}
__device__ __forceinline__ void unpack2(u64 v, float& a, float& b) {
    asm("mov.b64 {%0, %1}, %2;" : "=f"(a), "=f"(b) : "l"(v));
}
__device__ __forceinline__ u64 add2(u64 a, u64 b) {
    u64 r; asm("add.rn.f32x2 %0, %1, %2;" : "=l"(r) : "l"(a), "l"(b)); return r;
}
__device__ __forceinline__ u64 sub2(u64 a, u64 b) {
    u64 r; asm("sub.rn.f32x2 %0, %1, %2;" : "=l"(r) : "l"(a), "l"(b)); return r;
}
__device__ __forceinline__ u64 mul2(u64 a, u64 b) {
    u64 r; asm("mul.rn.f32x2 %0, %1, %2;" : "=l"(r) : "l"(a), "l"(b)); return r;
}
__device__ __forceinline__ u64 fma2(u64 a, u64 b, u64 c) {
    u64 r; asm("fma.rn.f32x2 %0, %1, %2, %3;" : "=l"(r) : "l"(a), "l"(b), "l"(c)); return r;
}

// 8-pt real FFT of |w| row, scales folded (bins 0,4 -> 1/8; bins 1-3 -> 1/4)
__device__ __forceinline__ void wspec(const float* __restrict__ wrow, float o[12]) {
    float x[8];
#pragma unroll
    for (int s = 0; s < 8; ++s) x[s] = fabsf(wrow[s]);
    float s0 = x[0] + x[4], s1 = x[0] - x[4], s2 = x[2] + x[6], s3 = x[2] - x[6];
    float t0 = x[1] + x[5], t1 = x[1] - x[5], t2 = x[3] + x[7], t3 = x[3] - x[7];
    float E0 = s0 + s2, O0 = t0 + t2;
    const float Cc = 0.70710678118654752f;
    float u = Cc * (t1 - t3), v = Cc * (t1 + t3);
    o[0]  = (E0 + O0) * 0.125f;
    o[1]  = (E0 - O0) * 0.125f;
    o[2]  = (s1 + u) * 0.25f;  o[3] = (-s3 - v) * 0.25f;  o[4]  = -o[3];
    o[5]  = (s0 - s2) * 0.25f; o[6] = (t2 - t0) * 0.25f;  o[7]  = -o[6];
    o[8]  = (s1 - u) * 0.25f;  o[9] = (s3 - v) * 0.25f;   o[10] = -o[9];
    o[11] = 0.0f;
}

// shared-rcp epilogue for a butterfly pair (4 phases, ONE rcp)
#define PAIR_EPILOGUE(YA, YB, ACCA, ACCB) do {                       \
    float phA0, phA1, phB0, phB1;                                    \
    unpack2((YA), phA0, phA1);                                       \
    unpack2((YB), phB0, phB1);                                       \
    float cA0 = __cosf(phA0), cA1 = __cosf(phA1);                    \
    float cB0 = __cosf(phB0), cB1 = __cosf(phB1);                    \
    float eA0 = fmaf(cA0, N2AR, C2), eA1 = fmaf(cA1, N2AR, C2);      \
    float eB0 = fmaf(cB0, N2AR, C2), eB1 = fmaf(cB1, N2AR, C2);      \
    float numA = fmaf(a1, eA0, a0 * eA1);                            \
    float denA = eA0 * eA1;                                          \
    float numB = fmaf(a1, eB0, a0 * eB1);                            \
    float denB = eB0 * eB1;                                          \
    float rr;                                                        \
    asm("rcp.approx.f32 %0, %1;" : "=f"(rr) : "f"(denA * denB));     \
    (ACCA) = fmaf(numA * denB, rr, (ACCA));                          \
    (ACCB) = fmaf(numB * denA, rr, (ACCB));                          \
} while (0)

// ---------------- fused kernel: x^2 tile in shared + FFT circulant ----------
// grid 1024, block 128. Block covers 32 pixels (same b,h; w = w0+lane).
// warp -> psplit (2 p's per thread), lane -> pixel.
__global__ __launch_bounds__(128, 7) void morr_kernel(const float* __restrict__ x,
                                                      const float* __restrict__ wgt,
                                                      const float* __restrict__ mos,
                                                      float* __restrict__ out) {
    __shared__ u64   wpk[NQP * PDIM * WSTR];  // packed {q0,q1} spectra, 13824 B
    __shared__ float xt[TILE_N];              // x^2 tile [c][kh][kw+lane], 13056 B
    __shared__ int   poff[QDIM * KB];         // tile offsets
    __shared__ float scl[QDIM];

    const int tid = threadIdx.x;

    // block coordinates: n0 = blockIdx*32 -> b, h fixed; w = w0 + lane
    const int b  = (int)blockIdx.x >> 7;
    const int h  = ((int)blockIdx.x >> 1) & 63;
    const int w0 = ((int)blockIdx.x & 1) * 32;

    // ---- load x^2 tile: x[b][c][h-1..h+1][w0-1..w0+32], zero-padded ----
    {
        const float* __restrict__ xbase = x + b * (IN_C * H_ * W_);
        for (int idx = tid; idx < TILE_N; idx += 128) {
            int c   = idx / CSTR;
            int rem = idx - c * CSTR;
            int kh  = rem / CTILE;
            int kw  = rem - kh * CTILE;
            int hr  = h + kh - 1;
            int wc  = w0 + kw - 1;
            float v = 0.0f;
            if ((unsigned)hr < 64u && (unsigned)wc < 64u) {
                float t = __ldg(&xbase[(c * H_ + hr) * W_ + wc]);
                v = t * t;
            }
            xt[idx] = v;
        }
    }

    // ---- weight spectra (144 (qp,p) pairs) ----
    for (int d = tid; d < NQP * PDIM; d += 128) {
        int qp = d >> 3;
        int p  = d & 7;
        float sA[12], sB[12];
        wspec(wgt + p * (QDIM * KB) + (2 * qp) * KB,     sA);
        wspec(wgt + p * (QDIM * KB) + (2 * qp + 1) * KB, sB);
        u64* o = &wpk[(qp * PDIM + p) * WSTR];
#pragma unroll
        for (int j = 0; j < 12; ++j) o[j] = pack2(sA[j], sB[j]);
    }
    // tile-offset table: i -> c*102 + kh*34 + kw  (add lane at gather time)
    for (int i = tid; i < QDIM * KB; i += 128) {
        int c = i / 9, r = i % 9;
        poff[i] = c * CSTR + (r / 3) * CTILE + (r % 3);
    }
    if (tid < QDIM) {
        const float D = (float)((1.0 - MRR_A * MRR_A) * (1.0 - MRR_R * MRR_R));
        float sv = (tid < QDIM / 2) ? mos[tid] : -mos[tid - QDIM / 2];
        scl[tid] = -D * sv;
    }
    __syncthreads();

    const int psplit = tid >> 5;
    const int lane   = tid & 31;

    const float* __restrict__ xbs = xt + lane;   // per-pixel base into tile

    float acc[2][8];
#pragma unroll
    for (int pl = 0; pl < 2; ++pl)
#pragma unroll
        for (int t = 0; t < 8; ++t) acc[pl][t] = 0.0f;

    const float C2   = (float)(1.0 + (MRR_A * MRR_R) * (MRR_A * MRR_R));
    const float N2AR = (float)(-2.0 * MRR_A * MRR_R);
    const float Cc = 0.70710678118654752f;
    const u64 CC2  = pack2(Cc, Cc);
    const u64 CCN2 = pack2(-Cc, -Cc);

    for (int qp = 0; qp < NQP; ++qp) {
        const float a0 = scl[2 * qp];
        const float a1 = scl[2 * qp + 1];

        // gather both q's inputs from the shared tile (conflict-free LDS)
        u64 xs[8];
#pragma unroll
        for (int s = 0; s < 8; ++s) {
            float x0 = xbs[poff[qp * 16 + s]];
            float x1 = xbs[poff[qp * 16 + 8 + s]];
            xs[s] = pack2(x0, x1);
        }

        // forward 8-pt real FFT (packed) — shared across both p's
        u64 s0 = add2(xs[0], xs[4]), s1 = sub2(xs[0], xs[4]);
        u64 s2 = add2(xs[2], xs[6]), s3 = sub2(xs[2], xs[6]);
        u64 t0 = add2(xs[1], xs[5]), t1 = sub2(xs[1], xs[5]);
        u64 t2 = add2(xs[3], xs[7]), t3 = sub2(xs[3], xs[7]);
        u64 E0 = add2(s0, s2), O0 = add2(t0, t2);
        u64 X0  = add2(E0, O0);
        u64 X4  = sub2(E0, O0);
        u64 X2r = sub2(s0, s2);
        u64 X2i = sub2(t2, t0);
        u64 um  = sub2(t1, t3), vp = add2(t1, t3);
        u64 u_  = mul2(CC2, um);
        u64 vn  = mul2(CCN2, vp);
        u64 X1r = add2(s1, u_);
        u64 X1i = sub2(vn, s3);
        u64 X3r = sub2(s1, u_);
        u64 X3i = add2(s3, vn);

#pragma unroll
        for (int pl = 0; pl < 2; ++pl) {
            const int p = psplit * 2 + pl;
            const u64* __restrict__ wq = &wpk[(qp * PDIM + p) * WSTR];

            u64 P0  = mul2(X0, wq[0]);
            u64 P4  = mul2(X4, wq[1]);
            u64 P1r = fma2(X1i, wq[4],  mul2(X1r, wq[2]));
            u64 P1i = fma2(X1r, wq[3],  mul2(X1i, wq[2]));
            u64 P2r = fma2(X2i, wq[7],  mul2(X2r, wq[5]));
            u64 P2i = fma2(X2r, wq[6],  mul2(X2i, wq[5]));
            u64 P3r = fma2(X3i, wq[10], mul2(X3r, wq[8]));
            u64 P3i = fma2(X3r, wq[9],  mul2(X3i, wq[8]));

            u64 A0 = add2(P0, P4), A1 = sub2(P0, P4);
            u64 e0 = add2(A0, P2r), e2 = sub2(A0, P2r);
            u64 e1 = sub2(A1, P2i), e3 = add2(A1, P2i);
            u64 o0 = add2(P1r, P3r);
            u64 o2 = sub2(P3i, P1i);
            u64 u2 = sub2(P1r, P3r), v2 = add2(P1i, P3i);
            u64 o1 = mul2(CC2,  sub2(u2, v2));
            u64 o3 = mul2(CCN2, add2(u2, v2));

            { u64 ya = add2(e0, o0), yb = sub2(e0, o0);
              PAIR_EPILOGUE(ya, yb, acc[pl][0], acc[pl][4]); }
            { u64 ya = add2(e1, o1), yb = sub2(e1, o1);
              PAIR_EPILOGUE(ya, yb, acc[pl][1], acc[pl][5]); }
            { u64 ya = add2(e2, o2), yb = sub2(e2, o2);
              PAIR_EPILOGUE(ya, yb, acc[pl][2], acc[pl][6]); }
            { u64 ya = add2(e3, o3), yb = sub2(e3, o3);
              PAIR_EPILOGUE(ya, yb, acc[pl][3], acc[pl][7]); }
        }
    }

    float* __restrict__ ob = out + (b * OUT_C + psplit * 16) * (H_ * W_)
                             + h * W_ + w0 + lane;
#pragma unroll
    for (int pl = 0; pl < 2; ++pl)
#pragma unroll
        for (int t = 0; t < 8; ++t)
            ob[(pl * 8 + t) * (H_ * W_)] = acc[pl][t];
}

// ---------------- launch ----------------
extern "C" void kernel_launch(void* const* d_in, const int* in_sizes, int n_in,
                              void* d_out, int out_size) {
    const float* x   = (const float*)d_in[0];
    const float* wgt = (const float*)d_in[1];
    const float* mos = (const float*)d_in[2];
    float* out = (float*)d_out;

    morr_kernel<<<NPIX / 32, 128>>>(x, wgt, mos, out);
}

// round 17
// speedup vs baseline: 1.1356x; 1.0007x over previous
#include <cuda_runtime.h>

// ---------------- problem constants ----------------
#define B_      8
#define IN_C    32
#define OUT_C   64
#define H_      64
#define W_      64
#define QDIM    36
#define PDIM    8
#define KB      8
#define NPIX    (B_*H_*W_)          // 32768
#define NQP     (QDIM/2)            // 18 q-pairs
#define WSTR    12                  // u64 entries per (qp,p) packed spectrum

#define CTILE   34                  // tile cols: w0-1 .. w0+32
#define TROWS   3                   // kh = 0..2
#define TILE_N  (IN_C*TROWS*CTILE)  // 3264 floats
#define CSTR    (TROWS*CTILE)       // 102 floats per channel in tile

#define MRR_A   0.987
#define MRR_R   0.99

typedef unsigned long long u64;

// ---------------- packed f32x2 helpers ----------------
__device__ __forceinline__ u64 pack2(float a, float b) {
    u64 r; asm("mov.b64 %0, {%1, %2};" : "=l"(r) : "f"(a), "f"(b)); return r;
}
__device__ __forceinline__ void unpack2(u64 v, float& a, float& b) {
    asm("mov.b64 {%0, %1}, %2;" : "=f"(a), "=f"(b) : "l"(v));
}
__device__ __forceinline__ u64 add2(u64 a, u64 b) {
    u64 r; asm("add.rn.f32x2 %0, %1, %2;" : "=l"(r) : "l"(a), "l"(b)); return r;
}
__device__ __forceinline__ u64 sub2(u64 a, u64 b) {
    u64 r; asm("sub.rn.f32x2 %0, %1, %2;" : "=l"(r) : "l"(a), "l"(b)); return r;
}
__device__ __forceinline__ u64 mul2(u64 a, u64 b) {
    u64 r; asm("mul.rn.f32x2 %0, %1, %2;" : "=l"(r) : "l"(a), "l"(b)); return r;
}
__device__ __forceinline__ u64 fma2(u64 a, u64 b, u64 c) {
    u64 r; asm("fma.rn.f32x2 %0, %1, %2, %3;" : "=l"(r) : "l"(a), "l"(b), "l"(c)); return r;
}

// 8-pt real FFT of |w| row, scales folded (bins 0,4 -> 1/8; bins 1-3 -> 1/4)
__device__ __forceinline__ void wspec(const float* __restrict__ wrow, float o[12]) {
    float x[8];
#pragma unroll
    for (int s = 0; s < 8; ++s) x[s] = fabsf(wrow[s]);
    float s0 = x[0] + x[4], s1 = x[0] - x[4], s2 = x[2] + x[6], s3 = x[2] - x[6];
    float t0 = x[1] + x[5], t1 = x[1] - x[5], t2 = x[3] + x[7], t3 = x[3] - x[7];
    float E0 = s0 + s2, O0 = t0 + t2;
    const float Cc = 0.70710678118654752f;
    float u = Cc * (t1 - t3), v = Cc * (t1 + t3);
    o[0]  = (E0 + O0) * 0.125f;
    o[1]  = (E0 - O0) * 0.125f;
    o[2]  = (s1 + u) * 0.25f;  o[3] = (-s3 - v) * 0.25f;  o[4]  = -o[3];
    o[5]  = (s0 - s2) * 0.25f; o[6] = (t2 - t0) * 0.25f;  o[7]  = -o[6];
    o[8]  = (s1 - u) * 0.25f;  o[9] = (s3 - v) * 0.25f;   o[10] = -o[9];
    o[11] = 0.0f;
}

// shared-rcp epilogue for a butterfly pair (4 phases, ONE rcp)
#define PAIR_EPILOGUE(YA, YB, ACCA, ACCB) do {                       \
    float phA0, phA1, phB0, phB1;                                    \
    unpack2((YA), phA0, phA1);                                       \
    unpack2((YB), phB0, phB1);                                       \
    float cA0 = __cosf(phA0), cA1 = __cosf(phA1);                    \
    float cB0 = __cosf(phB0), cB1 = __cosf(phB1);                    \
    float eA0 = fmaf(cA0, N2AR, C2), eA1 = fmaf(cA1, N2AR, C2);      \
    float eB0 = fmaf(cB0, N2AR, C2), eB1 = fmaf(cB1, N2AR, C2);      \
    float numA = fmaf(a1, eA0, a0 * eA1);                            \
    float denA = eA0 * eA1;                                          \
    float numB = fmaf(a1, eB0, a0 * eB1);                            \
    float denB = eB0 * eB1;                                          \
    float rr;                                                        \
    asm("rcp.approx.f32 %0, %1;" : "=f"(rr) : "f"(denA * denB));     \
    (ACCA) = fmaf(numA * denB, rr, (ACCA));                          \
    (ACCB) = fmaf(numB * denA, rr, (ACCB));                          \
} while (0)

// ---------------- fused kernel: x^2 tile in shared + FFT circulant ----------
// grid 1024, block 128. Block covers 32 pixels (same b,h; w = w0+lane).
// warp -> psplit (2 p's per thread), lane -> pixel.
__global__ __launch_bounds__(128, 7) void morr_kernel(const float* __restrict__ x,
                                                      const float* __restrict__ wgt,
                                                      const float* __restrict__ mos,
                                                      float* __restrict__ out) {
    __shared__ __align__(16) u64    wpk[NQP * PDIM * WSTR];  // packed spectra
    __shared__ __align__(16) float  xt[TILE_N];              // x^2 tile
    __shared__ __align__(16) int    poff[QDIM * KB];         // tile offsets
    __shared__ __align__(8)  float2 scl2[NQP];

    const int tid = threadIdx.x;

    const int b  = (int)blockIdx.x >> 7;
    const int h  = ((int)blockIdx.x >> 1) & 63;
    const int w0 = ((int)blockIdx.x & 1) * 32;

    // ---- load x^2 tile: x[b][c][h-1..h+1][w0-1..w0+32], zero-padded ----
    {
        const float* __restrict__ xbase = x + b * (IN_C * H_ * W_);
        for (int idx = tid; idx < TILE_N; idx += 128) {
            int c   = idx / CSTR;
            int rem = idx - c * CSTR;
            int kh  = rem / CTILE;
            int kw  = rem - kh * CTILE;
            int hr  = h + kh - 1;
            int wc  = w0 + kw - 1;
            float v = 0.0f;
            if ((unsigned)hr < 64u && (unsigned)wc < 64u) {
                float t = __ldg(&xbase[(c * H_ + hr) * W_ + wc]);
                v = t * t;
            }
            xt[idx] = v;
        }
    }

    // ---- weight spectra (144 (qp,p) pairs) ----
    for (int d = tid; d < NQP * PDIM; d += 128) {
        int qp = d >> 3;
        int p  = d & 7;
        float sA[12], sB[12];
        wspec(wgt + p * (QDIM * KB) + (2 * qp) * KB,     sA);
        wspec(wgt + p * (QDIM * KB) + (2 * qp + 1) * KB, sB);
        u64* o = &wpk[(qp * PDIM + p) * WSTR];
#pragma unroll
        for (int j = 0; j < 12; ++j) o[j] = pack2(sA[j], sB[j]);
    }
    // tile-offset table: i -> c*102 + kh*34 + kw  (add lane at gather time)
    for (int i = tid; i < QDIM * KB; i += 128) {
        int c = i / 9, r = i % 9;
        poff[i] = c * CSTR + (r / 3) * CTILE + (r % 3);
    }
    if (tid < NQP) {
        const float D = (float)((1.0 - MRR_A * MRR_A) * (1.0 - MRR_R * MRR_R));
        int q0 = 2 * tid, q1 = 2 * tid + 1;
        float sv0 = (q0 < QDIM / 2) ? mos[q0] : -mos[q0 - QDIM / 2];
        float sv1 = (q1 < QDIM / 2) ? mos[q1] : -mos[q1 - QDIM / 2];
        scl2[tid] = make_float2(-D * sv0, -D * sv1);
    }
    __syncthreads();

    const int psplit = tid >> 5;
    const int lane   = tid & 31;

    const float* __restrict__ xbs = xt + lane;   // per-pixel base into tile
    const int4* __restrict__ poff4 = reinterpret_cast<const int4*>(poff);

    float acc[2][8];
#pragma unroll
    for (int pl = 0; pl < 2; ++pl)
#pragma unroll
        for (int t = 0; t < 8; ++t) acc[pl][t] = 0.0f;

    const float C2   = (float)(1.0 + (MRR_A * MRR_R) * (MRR_A * MRR_R));
    const float N2AR = (float)(-2.0 * MRR_A * MRR_R);
    const float Cc = 0.70710678118654752f;
    const u64 CC2  = pack2(Cc, Cc);
    const u64 CCN2 = pack2(-Cc, -Cc);

#pragma unroll 2
    for (int qp = 0; qp < NQP; ++qp) {
        const float2 aa = scl2[qp];
        const float a0 = aa.x, a1 = aa.y;

        // 16 tile offsets via 4x LDS.128
        int4 pa0 = poff4[qp * 4 + 0];
        int4 pa1 = poff4[qp * 4 + 1];
        int4 pb0 = poff4[qp * 4 + 2];
        int4 pb1 = poff4[qp * 4 + 3];

        u64 xs[8];
        xs[0] = pack2(xbs[pa0.x], xbs[pb0.x]);
        xs[1] = pack2(xbs[pa0.y], xbs[pb0.y]);
        xs[2] = pack2(xbs[pa0.z], xbs[pb0.z]);
        xs[3] = pack2(xbs[pa0.w], xbs[pb0.w]);
        xs[4] = pack2(xbs[pa1.x], xbs[pb1.x]);
        xs[5] = pack2(xbs[pa1.y], xbs[pb1.y]);
        xs[6] = pack2(xbs[pa1.z], xbs[pb1.z]);
        xs[7] = pack2(xbs[pa1.w], xbs[pb1.w]);

        // forward 8-pt real FFT (packed) — shared across both p's
        u64 s0 = add2(xs[0], xs[4]), s1 = sub2(xs[0], xs[4]);
        u64 s2 = add2(xs[2], xs[6]), s3 = sub2(xs[2], xs[6]);
        u64 t0 = add2(xs[1], xs[5]), t1 = sub2(xs[1], xs[5]);
        u64 t2 = add2(xs[3], xs[7]), t3 = sub2(xs[3], xs[7]);
        u64 E0 = add2(s0, s2), O0 = add2(t0, t2);
        u64 X0  = add2(E0, O0);
        u64 X4  = sub2(E0, O0);
        u64 X2r = sub2(s0, s2);
        u64 X2i = sub2(t2, t0);
        u64 um  = sub2(t1, t3), vp = add2(t1, t3);
        u64 u_  = mul2(CC2, um);
        u64 vn  = mul2(CCN2, vp);
        u64 X1r = add2(s1, u_);
        u64 X1i = sub2(vn, s3);
        u64 X3r = sub2(s1, u_);
        u64 X3i = add2(s3, vn);

#pragma unroll
        for (int pl = 0; pl < 2; ++pl) {
            const int p = psplit * 2 + pl;
            const u64* __restrict__ wq = &wpk[(qp * PDIM + p) * WSTR];

            u64 P0  = mul2(X0, wq[0]);
            u64 P4  = mul2(X4, wq[1]);
            u64 P1r = fma2(X1i, wq[4],  mul2(X1r, wq[2]));
            u64 P1i = fma2(X1r, wq[3],  mul2(X1i, wq[2]));
            u64 P2r = fma2(X2i, wq[7],  mul2(X2r, wq[5]));
            u64 P2i = fma2(X2r, wq[6],  mul2(X2i, wq[5]));
            u64 P3r = fma2(X3i, wq[10], mul2(X3r, wq[8]));
            u64 P3i = fma2(X3r, wq[9],  mul2(X3i, wq[8]));

            u64 A0 = add2(P0, P4), A1 = sub2(P0, P4);
            u64 e0 = add2(A0, P2r), e2 = sub2(A0, P2r);
            u64 e1 = sub2(A1, P2i), e3 = add2(A1, P2i);
            u64 o0 = add2(P1r, P3r);
            u64 o2 = sub2(P3i, P1i);
            u64 u2 = sub2(P1r, P3r), v2 = add2(P1i, P3i);
            u64 o1 = mul2(CC2,  sub2(u2, v2));
            u64 o3 = mul2(CCN2, add2(u2, v2));

            { u64 ya = add2(e0, o0), yb = sub2(e0, o0);
              PAIR_EPILOGUE(ya, yb, acc[pl][0], acc[pl][4]); }
            { u64 ya = add2(e1, o1), yb = sub2(e1, o1);
              PAIR_EPILOGUE(ya, yb, acc[pl][1], acc[pl][5]); }
            { u64 ya = add2(e2, o2), yb = sub2(e2, o2);
              PAIR_EPILOGUE(ya, yb, acc[pl][2], acc[pl][6]); }
            { u64 ya = add2(e3, o3), yb = sub2(e3, o3);
              PAIR_EPILOGUE(ya, yb, acc[pl][3], acc[pl][7]); }
        }
    }

    float* __restrict__ ob = out + (b * OUT_C + psplit * 16) * (H_ * W_)
                             + h * W_ + w0 + lane;
#pragma unroll
    for (int pl = 0; pl < 2; ++pl)
#pragma unroll
        for (int t = 0; t < 8; ++t)
            ob[(pl * 8 + t) * (H_ * W_)] = acc[pl][t];
}

// ---------------- launch ----------------
extern "C" void kernel_launch(void* const* d_in, const int* in_sizes, int n_in,
                              void* d_out, int out_size) {
    const float* x   = (const float*)d_in[0];
    const float* wgt = (const float*)d_in[1];
    const float* mos = (const float*)d_in[2];
    float* out = (float*)d_out;

    morr_kernel<<<NPIX / 32, 128>>>(x, wgt, mos, out);
}